// round 6
// baseline (speedup 1.0000x reference)
#include <cuda_runtime.h>
#include <cstdint>

#define NN 100000
#define NE 1600000

__device__ int   g_mode;            // 0=int64, 1=int32, 2=float32 edge encoding
__device__ float g_deg[NN];         // degree -> dinv = rsqrt(deg)
__device__ float g_xs[NN * 8];      // xscaled = x * dinv (padded 6->8)
__device__ float g_agg1[NN * 8];    // layer-1 accumulator
__device__ float g_p[NN * 8];       // pscaled = (relu(h)@W2) * dinv
__device__ float g_out[NN * 8];     // layer-2 accumulator
__device__ int2  g_edge[NE];        // packed (src, dst)

__device__ __forceinline__ void red_add_v4(float* p, float a, float b, float c, float d) {
    asm volatile("red.global.add.v4.f32 [%0], {%1,%2,%3,%4};"
                 :: "l"(p), "f"(a), "f"(b), "f"(c), "f"(d) : "memory");
}
__device__ __forceinline__ void red_add_v2(float* p, float a, float b) {
    asm volatile("red.global.add.v2.f32 [%0], {%1,%2};"
                 :: "l"(p), "f"(a), "f"(b) : "memory");
}

// K1: block 0 probes edge dtype; all blocks zero agg1 (float4) and init deg=1
__global__ void k_init(const void* ei, int n) {
    if (blockIdx.x == 0) {
        __shared__ int ok64, okf;
        int t = threadIdx.x;
        if (t == 0) { ok64 = 1; okf = 1; }
        __syncthreads();
        const long long* p64 = (const long long*)ei;
        const float*     pf  = (const float*)ei;
        for (int i = t; i < 1024; i += blockDim.x) {
            long long v = p64[i];
            if (v < 0 || v >= NN) ok64 = 0;
            float f = pf[i];
            if (!(f >= 0.0f && f < (float)NN && f == floorf(f))) okf = 0;
        }
        __syncthreads();
        if (t == 0) g_mode = ok64 ? 0 : (okf ? 2 : 1);
    }
    int i = blockIdx.x * blockDim.x + threadIdx.x;
    if (i < n * 2) ((float4*)g_agg1)[i] = make_float4(0.f, 0.f, 0.f, 0.f);
    if (i < n)     g_deg[i] = 1.0f;
}

// K2: decode 4 edges/thread, pack 2x int4, clamp, count degree
__global__ void k_cvt(const void* ei, int E) {
    int t = blockIdx.x * blockDim.x + threadIdx.x;
    int e = t * 4;
    if (e >= E) return;
    int s[4], d[4];
    int mode = g_mode;
    if (mode == 0) {
        const longlong2* ps = (const longlong2*)ei;
        const longlong2* pd = (const longlong2*)((const long long*)ei + E);
        longlong2 sa = ps[t * 2], sb = ps[t * 2 + 1];
        longlong2 da = pd[t * 2], db = pd[t * 2 + 1];
        s[0] = (int)sa.x; s[1] = (int)sa.y; s[2] = (int)sb.x; s[3] = (int)sb.y;
        d[0] = (int)da.x; d[1] = (int)da.y; d[2] = (int)db.x; d[3] = (int)db.y;
    } else if (mode == 1) {
        const int4* ps = (const int4*)ei;
        const int4* pd = (const int4*)((const int*)ei + E);
        int4 sv = ps[t], dv = pd[t];
        s[0] = sv.x; s[1] = sv.y; s[2] = sv.z; s[3] = sv.w;
        d[0] = dv.x; d[1] = dv.y; d[2] = dv.z; d[3] = dv.w;
    } else {
        const float4* ps = (const float4*)ei;
        const float4* pd = (const float4*)((const float*)ei + E);
        float4 sv = ps[t], dv = pd[t];
        s[0] = (int)sv.x; s[1] = (int)sv.y; s[2] = (int)sv.z; s[3] = (int)sv.w;
        d[0] = (int)dv.x; d[1] = (int)dv.y; d[2] = (int)dv.z; d[3] = (int)dv.w;
    }
#pragma unroll
    for (int k = 0; k < 4; k++) {
        if ((unsigned)s[k] >= NN) s[k] = -1;
        if ((unsigned)d[k] >= NN) d[k] = -1;
    }
    int4* eo = (int4*)g_edge;
    eo[t * 2]     = make_int4(s[0], d[0], s[1], d[1]);
    eo[t * 2 + 1] = make_int4(s[2], d[2], s[3], d[3]);
#pragma unroll
    for (int k = 0; k < 4; k++)
        if (d[k] >= 0) atomicAdd(&g_deg[d[k]], 1.0f);
}

// K3: smem-staged: coalesced float4 read of 256 nodes' x, scale, write padded
__global__ void k_prep(const float* __restrict__ x, int n) {
    __shared__ float sx[256 * 6];
    int base = blockIdx.x * 256;          // first node of this block
    int t = threadIdx.x;
    // 256 nodes * 6 floats = 1536 floats = 384 float4, coalesced
    const float4* xin = (const float4*)(x + (size_t)base * 6);
    int nf4 = min(384, (n - base) * 6 / 4 + 1);
    for (int i = t; i < 384; i += 256) {
        if (base * 6 / 4 + i < (n * 6 + 3) / 4 && i < nf4 + 0) { }
        if ((size_t)(base * 6 + i * 4) < (size_t)n * 6)
            ((float4*)sx)[i] = xin[i];
    }
    __syncthreads();
    int v = base + t;
    if (v >= n) return;
    float di = rsqrtf(g_deg[v]);
    g_deg[v] = di;
    const float* xv = sx + t * 6;
    float4* o = (float4*)(g_xs + (size_t)v * 8);
    o[0] = make_float4(xv[0] * di, xv[1] * di, xv[2] * di, xv[3] * di);
    o[1] = make_float4(xv[4] * di, xv[5] * di, 0.0f, 0.0f);
}

// K4: layer-1 scatter, 2 edges/thread: agg1[d] += xscaled[s]
__global__ void k_scat1(int E2) {
    int t = blockIdx.x * blockDim.x + threadIdx.x;
    if (t >= E2) return;
    int4 e = ((const int4*)g_edge)[t];
    if (e.x >= 0 && e.y >= 0) {
        const float4* xs = (const float4*)(g_xs + (size_t)e.x * 8);
        float4 v0 = __ldg(xs);
        float2 v1 = __ldg((const float2*)(xs + 1));
        float* ag = g_agg1 + (size_t)e.y * 8;
        red_add_v4(ag,     v0.x, v0.y, v0.z, v0.w);
        red_add_v2(ag + 4, v1.x, v1.y);
    }
    if (e.z >= 0 && e.w >= 0) {
        const float4* xs = (const float4*)(g_xs + (size_t)e.z * 8);
        float4 v0 = __ldg(xs);
        float2 v1 = __ldg((const float2*)(xs + 1));
        float* ag = g_agg1 + (size_t)e.w * 8;
        red_add_v4(ag,     v0.x, v0.y, v0.z, v0.w);
        red_add_v2(ag + 4, v1.x, v1.y);
    }
}

// K5: a = di*(agg1 + xscaled); h = relu(a@W1+b1); p = h@W2; pscaled = p*di
__global__ void k_node(const float* __restrict__ W1, const float* __restrict__ b1,
                       const float* __restrict__ W2, int n) {
    __shared__ float sW1[6 * 64];
    __shared__ float sW2[64 * 8];
    __shared__ float sb1[64];
    for (int i = threadIdx.x; i < 6 * 64; i += blockDim.x) sW1[i] = W1[i];
    for (int i = threadIdx.x; i < 64 * 8; i += blockDim.x) sW2[i] = W2[i];
    for (int i = threadIdx.x; i < 64;     i += blockDim.x) sb1[i] = b1[i];
    __syncthreads();

    int v = blockIdx.x * blockDim.x + threadIdx.x;
    if (v >= n) return;

    float di = g_deg[v];
    const float4* ag = (const float4*)(g_agg1 + (size_t)v * 8);
    const float4* xs = (const float4*)(g_xs + (size_t)v * 8);
    float4 a0 = ag[0], a1 = ag[1];
    float4 x0 = xs[0], x1 = xs[1];

    float a[6];
    a[0] = di * (a0.x + x0.x);
    a[1] = di * (a0.y + x0.y);
    a[2] = di * (a0.z + x0.z);
    a[3] = di * (a0.w + x0.w);
    a[4] = di * (a1.x + x1.x);
    a[5] = di * (a1.y + x1.y);

    float p[8];
#pragma unroll
    for (int k = 0; k < 8; k++) p[k] = 0.0f;

#pragma unroll 8
    for (int j = 0; j < 64; j++) {
        float h = sb1[j];
#pragma unroll
        for (int i = 0; i < 6; i++) h = fmaf(a[i], sW1[i * 64 + j], h);
        h = fmaxf(h, 0.0f);
#pragma unroll
        for (int k = 0; k < 8; k++) p[k] = fmaf(h, sW2[j * 8 + k], p[k]);
    }

    float4 q0 = make_float4(p[0] * di, p[1] * di, p[2] * di, p[3] * di);
    float4 q1 = make_float4(p[4] * di, p[5] * di, p[6] * di, p[7] * di);
    float4* pr = (float4*)(g_p + (size_t)v * 8);
    float4* o  = (float4*)(g_out + (size_t)v * 8);
    pr[0] = q0; pr[1] = q1;
    o[0]  = q0; o[1]  = q1;   // self-loop seed (x di in k_final)
}

// K6: layer-2 scatter, 2 edges/thread: g_out[d] += pscaled[s]
__global__ void k_scat2(int E2) {
    int t = blockIdx.x * blockDim.x + threadIdx.x;
    if (t >= E2) return;
    int4 e = ((const int4*)g_edge)[t];
    if (e.x >= 0 && e.y >= 0) {
        const float4* ps = (const float4*)(g_p + (size_t)e.x * 8);
        float4 q0 = __ldg(ps);
        float4 q1 = __ldg(ps + 1);
        float* o = g_out + (size_t)e.y * 8;
        red_add_v4(o,     q0.x, q0.y, q0.z, q0.w);
        red_add_v4(o + 4, q1.x, q1.y, q1.z, q1.w);
    }
    if (e.z >= 0 && e.w >= 0) {
        const float4* ps = (const float4*)(g_p + (size_t)e.z * 8);
        float4 q0 = __ldg(ps);
        float4 q1 = __ldg(ps + 1);
        float* o = g_out + (size_t)e.w * 8;
        red_add_v4(o,     q0.x, q0.y, q0.z, q0.w);
        red_add_v4(o + 4, q1.x, q1.y, q1.z, q1.w);
    }
}

// K7: out[v] = di * accum[v] + b2
__global__ void k_final(const float* __restrict__ b2, float* __restrict__ out, int n) {
    int v = blockIdx.x * blockDim.x + threadIdx.x;
    if (v >= n) return;
    float di = g_deg[v];
    float4 bb0 = make_float4(b2[0], b2[1], b2[2], b2[3]);
    float4 bb1 = make_float4(b2[4], b2[5], b2[6], b2[7]);
    const float4* a = (const float4*)(g_out + (size_t)v * 8);
    float4 v0 = a[0], v1 = a[1];
    float4* o = (float4*)(out + (size_t)v * 8);
    o[0] = make_float4(fmaf(v0.x, di, bb0.x), fmaf(v0.y, di, bb0.y),
                       fmaf(v0.z, di, bb0.z), fmaf(v0.w, di, bb0.w));
    o[1] = make_float4(fmaf(v1.x, di, bb1.x), fmaf(v1.y, di, bb1.y),
                       fmaf(v1.z, di, bb1.z), fmaf(v1.w, di, bb1.w));
}

extern "C" void kernel_launch(void* const* d_in, const int* in_sizes, int n_in,
                              void* d_out, int out_size) {
    const float* x  = (const float*)d_in[0];
    const void*  ei = d_in[1];
    const float* W1 = (const float*)d_in[2];
    const float* b1 = (const float*)d_in[3];
    const float* W2 = (const float*)d_in[4];
    const float* b2 = (const float*)d_in[5];
    float*       out = (float*)d_out;

    const int N = NN;
    const int E = NE;

    k_init  <<<(N * 2 + 255) / 256, 256>>>(ei, N);
    k_cvt   <<<(E / 4 + 255) / 256, 256>>>(ei, E);
    k_prep  <<<(N + 255) / 256, 256>>>(x, N);
    k_scat1 <<<(E / 2 + 255) / 256, 256>>>(E / 2);
    k_node  <<<(N + 255) / 256, 256>>>(W1, b1, W2, N);
    k_scat2 <<<(E / 2 + 255) / 256, 256>>>(E / 2);
    k_final <<<(N + 255) / 256, 256>>>(b2, out, N);
}